// round 1
// baseline (speedup 1.0000x reference)
#include <cuda_runtime.h>
#include <math.h>

// Problem dims (fixed by dataset)
static constexpr int NMAX = 50000;
static constexpr int D    = 64;
static constexpr int C    = 64;   // embed out
static constexpr int K    = 500;  // assign out / clusters

// ---------------- scratch (device globals; no allocations allowed) ----------
__device__ float g_deg [NMAX];
__device__ float g_dinv[NMAX];
__device__ float g_hE  [NMAX * C];            // x @ W_embed + b
__device__ float g_zE  [NMAX * C];            // GCN(embed)
__device__ float g_hA  [(long)NMAX * K];      // x @ W_assign + b
__device__ float g_S   [(long)NMAX * K];      // GCN(assign) -> softmax in place
__device__ float g_AS  [(long)NMAX * K];      // A @ S

// ---------------- small utility kernels ------------------------------------
__global__ void k_zero_out(float* out, int total) {
    int i = blockIdx.x * blockDim.x + threadIdx.x;
    if (i < total) out[i] = 0.0f;
}

__global__ void k_zero_AS(long total) {
    long i = (long)blockIdx.x * blockDim.x + threadIdx.x;
    if (i < total) g_AS[i] = 0.0f;
}

__global__ void k_deg_init(int n) {
    int i = blockIdx.x * blockDim.x + threadIdx.x;
    if (i < n) g_deg[i] = 1.0f;  // self loop
}

__global__ void k_deg_count(const int* __restrict__ row, int e) {
    int i = blockIdx.x * blockDim.x + threadIdx.x;
    if (i < e) atomicAdd(&g_deg[row[i]], 1.0f);
}

__global__ void k_dinv(int n) {
    int i = blockIdx.x * blockDim.x + threadIdx.x;
    if (i < n) g_dinv[i] = rsqrtf(g_deg[i]);
}

// ---------------- h = x @ W + b  (D = 64 fixed) -----------------------------
// MODE 0 -> g_hE (COUT=C), MODE 1 -> g_hA (COUT=K)
template <int MODE>
__global__ __launch_bounds__(256) void k_xw(const float* __restrict__ x,
                                            const float* __restrict__ W,
                                            const float* __restrict__ b, int n) {
    constexpr int COUT = (MODE == 0) ? C : K;
    float* out = (MODE == 0) ? g_hE : g_hA;

    __shared__ float xs[64][65];
    __shared__ float ws[64][65];

    int n0 = blockIdx.y * 64;
    int c0 = blockIdx.x * 64;
    int tid = threadIdx.x;

    for (int i = tid; i < 64 * 64; i += 256) {
        int r = i >> 6, c = i & 63;
        int nn = n0 + r;
        xs[r][c] = (nn < n) ? x[(long)nn * D + c] : 0.0f;
    }
    for (int i = tid; i < 64 * 64; i += 256) {
        int r = i >> 6, c = i & 63;
        int cc = c0 + c;
        ws[r][c] = (cc < COUT) ? W[r * COUT + cc] : 0.0f;
    }
    __syncthreads();

    int tx = tid & 15, ty = tid >> 4;
    float acc[4][4] = {};
#pragma unroll
    for (int k = 0; k < 64; k++) {
        float a[4], bb[4];
#pragma unroll
        for (int i = 0; i < 4; i++) a[i] = xs[ty * 4 + i][k];
#pragma unroll
        for (int j = 0; j < 4; j++) bb[j] = ws[k][tx * 4 + j];
#pragma unroll
        for (int i = 0; i < 4; i++)
#pragma unroll
            for (int j = 0; j < 4; j++) acc[i][j] += a[i] * bb[j];
    }

#pragma unroll
    for (int i = 0; i < 4; i++) {
        int nn = n0 + ty * 4 + i;
        if (nn >= n) continue;
#pragma unroll
        for (int j = 0; j < 4; j++) {
            int cc = c0 + tx * 4 + j;
            if (cc < COUT) out[(long)nn * COUT + cc] = acc[i][j] + b[cc];
        }
    }
}

// ---------------- z[i] = dinv[i]^2 * h[i]  (self-loop term) -----------------
// MODE 0: g_zE = dinv^2 * g_hE ; MODE 1: g_S = dinv^2 * g_hA
template <int MODE>
__global__ void k_selfinit(int n) {
    constexpr int COUT = (MODE == 0) ? C : K;
    const float* h = (MODE == 0) ? g_hE : g_hA;
    float* z = (MODE == 0) ? g_zE : g_S;
    long idx = (long)blockIdx.x * blockDim.x + threadIdx.x;
    long total = (long)n * COUT;
    if (idx < total) {
        int nn = (int)(idx / COUT);
        float dv = g_dinv[nn];
        z[idx] = dv * dv * h[idx];
    }
}

// ---------------- edge scatter-aggregate ------------------------------------
// MODE 0: g_zE[s] += dinv[g]*dinv[s]*g_hE[g]   (gather=row, scatter=col)
// MODE 1: g_S [s] += dinv[g]*dinv[s]*g_hA[g]   (gather=row, scatter=col)
// MODE 2: g_AS[s] += g_S[g]                    (gather=col, scatter=row)
template <int MODE>
__global__ __launch_bounds__(256) void k_scatter(const int* __restrict__ gidx,
                                                 const int* __restrict__ sidx,
                                                 int e) {
    constexpr int COUT = (MODE == 0) ? C : K;
    constexpr int C4 = COUT / 4;
    const float* h = (MODE == 0) ? g_hE : (MODE == 1) ? g_hA : g_S;
    float* z = (MODE == 0) ? g_zE : (MODE == 1) ? g_S : g_AS;

    int warp = (blockIdx.x * blockDim.x + threadIdx.x) >> 5;
    int lane = threadIdx.x & 31;
    if (warp >= e) return;

    int g = __ldg(&gidx[warp]);
    int s = __ldg(&sidx[warp]);
    float w = 1.0f;
    if (MODE < 2) w = g_dinv[g] * g_dinv[s];

    const float4* h4 = reinterpret_cast<const float4*>(h + (long)g * COUT);
    float* zp = z + (long)s * COUT;

#pragma unroll
    for (int v = lane; v < C4; v += 32) {
        float4 hv = __ldg(&h4[v]);
        float* p = zp + 4 * v;
        asm volatile("red.global.add.v4.f32 [%0], {%1,%2,%3,%4};"
                     :: "l"(p), "f"(w * hv.x), "f"(w * hv.y),
                        "f"(w * hv.z), "f"(w * hv.w)
                     : "memory");
    }
}

// ---------------- row softmax of g_S (K = 500) ------------------------------
__global__ __launch_bounds__(256) void k_softmax(int n) {
    int row = blockIdx.x * 8 + (threadIdx.x >> 5);
    int lane = threadIdx.x & 31;
    if (row >= n) return;
    float* p = g_S + (long)row * K;

    float vals[16];
    float m = -1e30f;
#pragma unroll
    for (int i = 0; i < 16; i++) {
        int c = lane + i * 32;
        vals[i] = (c < K) ? p[c] : -1e30f;
        m = fmaxf(m, vals[i]);
    }
#pragma unroll
    for (int off = 16; off > 0; off >>= 1)
        m = fmaxf(m, __shfl_xor_sync(0xffffffffu, m, off));

    float sum = 0.0f;
#pragma unroll
    for (int i = 0; i < 16; i++) {
        int c = lane + i * 32;
        vals[i] = (c < K) ? expf(vals[i] - m) : 0.0f;
        sum += vals[i];
    }
#pragma unroll
    for (int off = 16; off > 0; off >>= 1)
        sum += __shfl_xor_sync(0xffffffffu, sum, off);

    float inv = 1.0f / sum;
#pragma unroll
    for (int i = 0; i < 16; i++) {
        int c = lane + i * 32;
        if (c < K) p[c] = vals[i] * inv;
    }
}

// ---------------- out = S^T @ M  (split-K, atomic epilogue) -----------------
// MODE 0: M = g_zE (COUT=C), writes out[0 .. K*C)
// MODE 1: M = g_AS (COUT=K), writes out[K*C .. K*C + K*K)
template <int MODE>
__global__ __launch_bounds__(256) void k_stm(float* __restrict__ out_base, int n,
                                             int nPerSplit) {
    constexpr int COUT = (MODE == 0) ? C : K;
    const float* Mp = (MODE == 0) ? g_zE : g_AS;
    float* out = (MODE == 0) ? out_base : out_base + K * C;

    __shared__ float Ss[32][65];
    __shared__ float Ms[32][65];

    int c0 = blockIdx.x * 64;
    int k0 = blockIdx.y * 64;
    int nStart = blockIdx.z * nPerSplit;
    int nEnd = min(n, nStart + nPerSplit);
    int tid = threadIdx.x;
    int tx = tid & 15, ty = tid >> 4;

    float acc[4][4] = {};

    for (int nb = nStart; nb < nEnd; nb += 32) {
        for (int i = tid; i < 32 * 64; i += 256) {
            int r = i >> 6, c = i & 63;
            int nn = nb + r;
            int kk = k0 + c;
            Ss[r][c] = (nn < nEnd && kk < K) ? g_S[(long)nn * K + kk] : 0.0f;
        }
        for (int i = tid; i < 32 * 64; i += 256) {
            int r = i >> 6, c = i & 63;
            int nn = nb + r;
            int cc = c0 + c;
            Ms[r][c] = (nn < nEnd && cc < COUT) ? Mp[(long)nn * COUT + cc] : 0.0f;
        }
        __syncthreads();

#pragma unroll 8
        for (int r = 0; r < 32; r++) {
            float a[4], bb[4];
#pragma unroll
            for (int i = 0; i < 4; i++) a[i] = Ss[r][ty * 4 + i];
#pragma unroll
            for (int j = 0; j < 4; j++) bb[j] = Ms[r][tx * 4 + j];
#pragma unroll
            for (int i = 0; i < 4; i++)
#pragma unroll
                for (int j = 0; j < 4; j++) acc[i][j] += a[i] * bb[j];
        }
        __syncthreads();
    }

#pragma unroll
    for (int i = 0; i < 4; i++) {
        int kk = k0 + ty * 4 + i;
        if (kk >= K) continue;
#pragma unroll
        for (int j = 0; j < 4; j++) {
            int cc = c0 + tx * 4 + j;
            if (cc < COUT) atomicAdd(&out[(long)kk * COUT + cc], acc[i][j]);
        }
    }
}

// ---------------- launch -----------------------------------------------------
extern "C" void kernel_launch(void* const* d_in, const int* in_sizes, int n_in,
                              void* d_out, int out_size) {
    const float* x  = (const float*)d_in[0];
    const int*   ei = (const int*)d_in[1];
    const float* We = (const float*)d_in[2];
    const float* be = (const float*)d_in[3];
    const float* Wa = (const float*)d_in[4];
    const float* ba = (const float*)d_in[5];
    float* out = (float*)d_out;

    int n = in_sizes[0] / D;
    int e = in_sizes[1] / 2;
    const int* row = ei;       // source j
    const int* col = ei + e;   // target i

    // zero output (poisoned by harness)
    k_zero_out<<<(out_size + 511) / 512, 512>>>(out, out_size);

    // degrees (row-based + self loop) and dinv
    k_deg_init<<<(n + 255) / 256, 256>>>(n);
    k_deg_count<<<(e + 255) / 256, 256>>>(row, e);
    k_dinv<<<(n + 255) / 256, 256>>>(n);

    // h = x @ W + b
    {
        dim3 gE((C + 63) / 64, (n + 63) / 64);
        k_xw<0><<<gE, 256>>>(x, We, be, n);
        dim3 gA((K + 63) / 64, (n + 63) / 64);
        k_xw<1><<<gA, 256>>>(x, Wa, ba, n);
    }

    // self-loop init of Z buffers
    {
        long tE = (long)n * C;
        k_selfinit<0><<<(int)((tE + 255) / 256), 256>>>(n);
        long tA = (long)n * K;
        k_selfinit<1><<<(int)((tA + 255) / 256), 256>>>(n);
    }

    // GCN edge aggregation (gather row -> scatter col, normalized)
    {
        int blocks = (e + 7) / 8;  // 8 warps/block, warp per edge
        k_scatter<0><<<blocks, 256>>>(row, col, e);
        k_scatter<1><<<blocks, 256>>>(row, col, e);
    }

    // S = softmax(Z_assign) rowwise
    k_softmax<<<(n + 7) / 8, 256>>>(n);

    // AS = A @ S : zero then scatter (gather col -> scatter row, unnormalized)
    {
        long tA = (long)n * K;
        k_zero_AS<<<(int)((tA + 255) / 256), 256>>>(tA);
        int blocks = (e + 7) / 8;
        k_scatter<2><<<blocks, 256>>>(col, row, e);
    }

    // next_X = S^T @ Z_embed   [K, C]
    {
        int splits = 50;
        int nPer = (n + splits - 1) / splits;
        dim3 g((C + 63) / 64, (K + 63) / 64, splits);
        k_stm<0><<<g, 256>>>(out, n, nPer);
    }
    // next_A = S^T @ AS        [K, K]
    {
        int splits = 25;
        int nPer = (n + splits - 1) / splits;
        dim3 g((K + 63) / 64, (K + 63) / 64, splits);
        k_stm<1><<<g, 256>>>(out, n, nPer);
    }
}

// round 2
// speedup vs baseline: 1.5350x; 1.5350x over previous
#include <cuda_runtime.h>
#include <math.h>
#include <stdint.h>

// Problem dims (fixed by dataset)
static constexpr int NMAX = 50000;
static constexpr int D    = 64;
static constexpr int C    = 64;   // embed out
static constexpr int K    = 500;  // assign out / clusters

// ---------------- scratch (device globals; no allocations allowed) ----------
__device__ float g_deg [NMAX];
__device__ float g_dinv[NMAX];
__device__ float g_ctmp[NMAX];
__device__ float g_c   [NMAX];
__device__ float g_px  [NMAX * D];            // P @ x
__device__ float g_zE  [NMAX * C];            // GCN(embed) = px@We + c be^T
__device__ float g_S   [(long)NMAX * K];      // GCN(assign) -> softmax in place
__device__ float g_AS  [(long)NMAX * K];      // A @ S

// ---------------- small utility kernels ------------------------------------
__global__ void k_zero_out(float* out, int total) {
    int i = blockIdx.x * blockDim.x + threadIdx.x;
    if (i < total) out[i] = 0.0f;
}

__global__ void k_zero_AS(long total4) {
    long i = (long)blockIdx.x * blockDim.x + threadIdx.x;
    if (i < total4)
        reinterpret_cast<float4*>(g_AS)[i] = make_float4(0.f, 0.f, 0.f, 0.f);
}

__global__ void k_deg_init(int n) {
    int i = blockIdx.x * blockDim.x + threadIdx.x;
    if (i < n) { g_deg[i] = 1.0f; g_ctmp[i] = 0.0f; }  // self loop
}

__global__ void k_deg_count(const int* __restrict__ row, int e) {
    int i = blockIdx.x * blockDim.x + threadIdx.x;
    if (i < e) atomicAdd(&g_deg[row[i]], 1.0f);
}

__global__ void k_dinv(int n) {
    int i = blockIdx.x * blockDim.x + threadIdx.x;
    if (i < n) g_dinv[i] = rsqrtf(g_deg[i]);
}

// c_tmp[col] += dinv[row]   (for the bias coefficient c = P @ 1)
__global__ void k_coef(const int* __restrict__ row, const int* __restrict__ col, int e) {
    int i = blockIdx.x * blockDim.x + threadIdx.x;
    if (i < e) atomicAdd(&g_ctmp[col[i]], g_dinv[row[i]]);
}

__global__ void k_cfin(int n) {
    int i = blockIdx.x * blockDim.x + threadIdx.x;
    if (i < n) {
        float dv = g_dinv[i];
        g_c[i] = dv * (dv + g_ctmp[i]);
    }
}

// px = dinv^2 * x (self-loop term of P @ x); float4 over n*16
__global__ void k_px_self(const float* __restrict__ x, int n) {
    long i = (long)blockIdx.x * blockDim.x + threadIdx.x;
    if (i < (long)n * 16) {
        float dv = g_dinv[i >> 4];
        float w = dv * dv;
        float4 v = __ldg(reinterpret_cast<const float4*>(x) + i);
        reinterpret_cast<float4*>(g_px)[i] =
            make_float4(w * v.x, w * v.y, w * v.z, w * v.w);
    }
}

// px[col] += dinv[row]*dinv[col] * x[row]; 16 lanes per edge (64 floats)
__global__ __launch_bounds__(256) void k_scatter_px(const int* __restrict__ row,
                                                    const int* __restrict__ col,
                                                    const float* __restrict__ x, int e) {
    int t = blockIdx.x * 256 + threadIdx.x;
    int eidx = t >> 4;
    int lane = t & 15;
    if (eidx >= e) return;
    int g = __ldg(&row[eidx]);
    int s = __ldg(&col[eidx]);
    float w = g_dinv[g] * g_dinv[s];
    float4 v = __ldg(reinterpret_cast<const float4*>(x + (long)g * D) + lane);
    float* p = g_px + (long)s * D + lane * 4;
    asm volatile("red.global.add.v4.f32 [%0], {%1,%2,%3,%4};"
                 :: "l"(p), "f"(w * v.x), "f"(w * v.y), "f"(w * v.z), "f"(w * v.w)
                 : "memory");
}

// ---------------- Z = px @ W + c * b^T  (K-dim = 64 fixed) ------------------
// MODE 0 -> g_zE (COUT=C), MODE 1 -> g_S (COUT=K)
template <int MODE>
__global__ __launch_bounds__(256) void k_xw(const float* __restrict__ W,
                                            const float* __restrict__ b, int n) {
    constexpr int COUT = (MODE == 0) ? C : K;
    float* out = (MODE == 0) ? g_zE : g_S;

    __shared__ float xs[64][65];
    __shared__ float ws[64][65];

    int n0 = blockIdx.y * 64;
    int c0 = blockIdx.x * 64;
    int tid = threadIdx.x;

    for (int i = tid; i < 64 * 64; i += 256) {
        int r = i >> 6, c = i & 63;
        int nn = n0 + r;
        xs[r][c] = (nn < n) ? g_px[(long)nn * D + c] : 0.0f;
    }
    for (int i = tid; i < 64 * 64; i += 256) {
        int r = i >> 6, c = i & 63;
        int cc = c0 + c;
        ws[r][c] = (cc < COUT) ? W[r * COUT + cc] : 0.0f;
    }
    __syncthreads();

    int tx = tid & 15, ty = tid >> 4;
    float acc[4][4] = {};
#pragma unroll
    for (int k = 0; k < 64; k++) {
        float a[4], bb[4];
#pragma unroll
        for (int i = 0; i < 4; i++) a[i] = xs[ty * 4 + i][k];
#pragma unroll
        for (int j = 0; j < 4; j++) bb[j] = ws[k][tx * 4 + j];
#pragma unroll
        for (int i = 0; i < 4; i++)
#pragma unroll
            for (int j = 0; j < 4; j++) acc[i][j] += a[i] * bb[j];
    }

#pragma unroll
    for (int i = 0; i < 4; i++) {
        int nn = n0 + ty * 4 + i;
        if (nn >= n) continue;
        float cv = g_c[nn];
#pragma unroll
        for (int j = 0; j < 4; j++) {
            int cc = c0 + tx * 4 + j;
            if (cc < COUT) out[(long)nn * COUT + cc] = acc[i][j] + cv * b[cc];
        }
    }
}

// ---------------- row softmax of g_S (K = 500) ------------------------------
__global__ __launch_bounds__(256) void k_softmax(int n) {
    int row = blockIdx.x * 8 + (threadIdx.x >> 5);
    int lane = threadIdx.x & 31;
    if (row >= n) return;
    float* p = g_S + (long)row * K;

    float vals[16];
    float m = -1e30f;
#pragma unroll
    for (int i = 0; i < 16; i++) {
        int c = lane + i * 32;
        vals[i] = (c < K) ? p[c] : -1e30f;
        m = fmaxf(m, vals[i]);
    }
#pragma unroll
    for (int off = 16; off > 0; off >>= 1)
        m = fmaxf(m, __shfl_xor_sync(0xffffffffu, m, off));

    float sum = 0.0f;
#pragma unroll
    for (int i = 0; i < 16; i++) {
        int c = lane + i * 32;
        vals[i] = (c < K) ? expf(vals[i] - m) : 0.0f;
        sum += vals[i];
    }
#pragma unroll
    for (int off = 16; off > 0; off >>= 1)
        sum += __shfl_xor_sync(0xffffffffu, sum, off);

    float inv = 1.0f / sum;
#pragma unroll
    for (int i = 0; i < 16; i++) {
        int c = lane + i * 32;
        if (c < K) p[c] = vals[i] * inv;
    }
}

// ---------------- AS[row] += S[col] (warp per edge) -------------------------
__global__ __launch_bounds__(256) void k_scatter_AS(const int* __restrict__ gidx,
                                                    const int* __restrict__ sidx, int e) {
    int warp = (blockIdx.x * 256 + threadIdx.x) >> 5;
    int lane = threadIdx.x & 31;
    if (warp >= e) return;
    int g = __ldg(&gidx[warp]);
    int s = __ldg(&sidx[warp]);
    const float4* h4 = reinterpret_cast<const float4*>(g_S + (long)g * K);
    float* zp = g_AS + (long)s * K;
#pragma unroll
    for (int v = lane; v < K / 4; v += 32) {
        float4 hv = __ldg(&h4[v]);
        float* p = zp + 4 * v;
        asm volatile("red.global.add.v4.f32 [%0], {%1,%2,%3,%4};"
                     :: "l"(p), "f"(hv.x), "f"(hv.y), "f"(hv.z), "f"(hv.w)
                     : "memory");
    }
}

// ---------------- out = S^T @ M  (f32x2 packed, split-K, atomic epilogue) ----
// MODE 0: M = g_zE (COUT=C=64, BN=64), out[0 .. K*C)
// MODE 1: M = g_AS (COUT=K=500, BN=128), out[K*C ..)
template <int MODE>
__global__ __launch_bounds__(256) void k_stm(float* __restrict__ out_base, int n,
                                             int nPerSplit) {
    constexpr int COUT = (MODE == 0) ? C : K;
    constexpr int BN = (MODE == 0) ? 64 : 128;
    constexpr int TN = BN / 16;          // cols per thread (4 or 8)
    constexpr int BM = 128;
    constexpr int BK = 32;
    const float* __restrict__ Mp = (MODE == 0) ? g_zE : g_AS;
    float* __restrict__ out = (MODE == 0) ? out_base : out_base + K * C;

    __shared__ float Ss[BK][BM];
    __shared__ float Ms[BK][BN];

    const int m0 = blockIdx.y * BM;
    const int n0 = blockIdx.x * BN;
    const int nStart = blockIdx.z * nPerSplit;
    const int nEnd = min(n, nStart + nPerSplit);
    const int tid = threadIdx.x;
    const int txm = tid & 15;
    const int tyn = tid >> 4;

    unsigned long long acc[2][2][TN];
#pragma unroll
    for (int a = 0; a < 2; a++)
#pragma unroll
        for (int p = 0; p < 2; p++)
#pragma unroll
            for (int j = 0; j < TN; j++) acc[a][p][j] = 0ull;

    uint32_t sS = (uint32_t)__cvta_generic_to_shared((void*)&Ss[0][0]);

    for (int nb = nStart; nb < nEnd; nb += BK) {
        // stage S tile: BK x BM (m-contiguous)
        for (int i = tid; i < BK * (BM / 4); i += 256) {
            int r = i >> 5;                 // BM/4 == 32
            int c4 = i & 31;
            int kk = nb + r;
            int mf4 = (m0 >> 2) + c4;
            float4 v = make_float4(0.f, 0.f, 0.f, 0.f);
            if (kk < nEnd && mf4 < (K >> 2))
                v = *reinterpret_cast<const float4*>(g_S + (long)kk * K + (mf4 << 2));
            *reinterpret_cast<float4*>(&Ss[r][c4 << 2]) = v;
        }
        // stage M tile: BK x BN
        for (int i = tid; i < BK * (BN / 4); i += 256) {
            int r = i / (BN / 4);
            int c4 = i % (BN / 4);
            int kk = nb + r;
            int cf4 = (n0 >> 2) + c4;
            float4 v = make_float4(0.f, 0.f, 0.f, 0.f);
            if (kk < nEnd && cf4 < (COUT >> 2))
                v = *reinterpret_cast<const float4*>(Mp + (long)kk * COUT + (cf4 << 2));
            *reinterpret_cast<float4*>(&Ms[r][c4 << 2]) = v;
        }
        __syncthreads();

#pragma unroll 8
        for (int kk = 0; kk < BK; kk++) {
            unsigned long long a2[2][2];
#pragma unroll
            for (int ch = 0; ch < 2; ch++)
#pragma unroll
                for (int p = 0; p < 2; p++) {
                    uint32_t addr = sS + ((kk * BM + ch * 64 + txm * 4 + p * 2) << 2);
                    asm volatile("ld.shared.b64 %0, [%1];" : "=l"(a2[ch][p]) : "r"(addr));
                }
            float bv[TN];
#pragma unroll
            for (int j4 = 0; j4 < TN / 4; j4++) {
                float4 b4 = *reinterpret_cast<const float4*>(&Ms[kk][tyn * TN + j4 * 4]);
                bv[j4 * 4 + 0] = b4.x; bv[j4 * 4 + 1] = b4.y;
                bv[j4 * 4 + 2] = b4.z; bv[j4 * 4 + 3] = b4.w;
            }
#pragma unroll
            for (int j = 0; j < TN; j++) {
                unsigned long long bb;
                asm("mov.b64 %0, {%1, %2};" : "=l"(bb) : "f"(bv[j]), "f"(bv[j]));
#pragma unroll
                for (int ch = 0; ch < 2; ch++)
#pragma unroll
                    for (int p = 0; p < 2; p++)
                        asm("fma.rn.f32x2 %0, %1, %2, %0;"
                            : "+l"(acc[ch][p][j]) : "l"(a2[ch][p]), "l"(bb));
            }
        }
        __syncthreads();
    }

    // epilogue: atomics into out (zeroed up front)
#pragma unroll
    for (int ch = 0; ch < 2; ch++)
#pragma unroll
        for (int p = 0; p < 2; p++)
#pragma unroll
            for (int j = 0; j < TN; j++) {
                float lo, hi;
                asm("mov.b64 {%0, %1}, %2;" : "=f"(lo), "=f"(hi) : "l"(acc[ch][p][j]));
                int m = m0 + ch * 64 + txm * 4 + p * 2;
                int nn = n0 + tyn * TN + j;
                if (nn < COUT) {
                    if (m < K)     atomicAdd(&out[(long)m * COUT + nn], lo);
                    if (m + 1 < K) atomicAdd(&out[(long)(m + 1) * COUT + nn], hi);
                }
            }
}

// ---------------- launch -----------------------------------------------------
extern "C" void kernel_launch(void* const* d_in, const int* in_sizes, int n_in,
                              void* d_out, int out_size) {
    const float* x  = (const float*)d_in[0];
    const int*   ei = (const int*)d_in[1];
    const float* We = (const float*)d_in[2];
    const float* be = (const float*)d_in[3];
    const float* Wa = (const float*)d_in[4];
    const float* ba = (const float*)d_in[5];
    float* out = (float*)d_out;

    int n = in_sizes[0] / D;
    int e = in_sizes[1] / 2;
    const int* row = ei;       // source j
    const int* col = ei + e;   // target i

    // zero output (poisoned by harness)
    k_zero_out<<<(out_size + 511) / 512, 512>>>(out, out_size);

    // degrees (row-based + self loop), dinv
    k_deg_init<<<(n + 255) / 256, 256>>>(n);
    k_deg_count<<<(e + 255) / 256, 256>>>(row, e);
    k_dinv<<<(n + 255) / 256, 256>>>(n);

    // px = P @ x  (self-loop init + 64-wide edge scatter)
    k_px_self<<<(n * 16 + 255) / 256, 256>>>(x, n);
    k_scatter_px<<<(e * 16 + 255) / 256, 256>>>(row, col, x, e);

    // c = P @ 1 (bias coefficient)
    k_coef<<<(e + 255) / 256, 256>>>(row, col, e);
    k_cfin<<<(n + 255) / 256, 256>>>(n);

    // Z_assign = px@Wa + c ba^T ; Z_embed = px@We + c be^T
    {
        dim3 gA((K + 63) / 64, (n + 63) / 64);
        k_xw<1><<<gA, 256>>>(Wa, ba, n);
        dim3 gE((C + 63) / 64, (n + 63) / 64);
        k_xw<0><<<gE, 256>>>(We, be, n);
    }

    // S = softmax(Z_assign) rowwise
    k_softmax<<<(n + 7) / 8, 256>>>(n);

    // AS = A @ S
    {
        long total4 = (long)n * K / 4;
        k_zero_AS<<<(int)((total4 + 255) / 256), 256>>>(total4);
        k_scatter_AS<<<(e + 7) / 8, 256>>>(col, row, e);
    }

    // next_X = S^T @ Z_embed  [K, C]
    {
        int splits = 72;
        int nPer = (n + splits - 1) / splits;
        dim3 g(1, 4, splits);
        k_stm<0><<<g, 256>>>(out, n, nPer);
    }
    // next_A = S^T @ AS       [K, K]
    {
        int splits = 18;
        int nPer = (n + splits - 1) / splits;
        dim3 g(4, 4, splits);
        k_stm<1><<<g, 256>>>(out, n, nPer);
    }
}

// round 3
// speedup vs baseline: 2.9087x; 1.8949x over previous
#include <cuda_runtime.h>
#include <cuda_bf16.h>
#include <math.h>
#include <stdint.h>

// Problem dims (fixed by dataset)
static constexpr int NMAX = 50000;
static constexpr int D    = 64;
static constexpr int C    = 64;   // embed out
static constexpr int K    = 500;  // assign out / clusters
static constexpr int KP   = 512;  // padded K for bf16 GEMM
static constexpr int EMAX = 800000;

// ---------------- scratch (device globals; no allocations allowed) ----------
__device__ float g_dinv[NMAX];
__device__ float g_ctmp[NMAX];
__device__ float g_c   [NMAX];
__device__ int   g_cnt [NMAX];
__device__ int   g_off [NMAX + 1];
__device__ int   g_cur [NMAX];
__device__ int   g_eidx[EMAX];
__device__ float g_px  [NMAX * D];                    // P @ x
__device__ float g_zE  [NMAX * C];                    // GCN(embed)
__device__ float g_S   [(long)NMAX * K];              // GCN(assign) -> softmax (f32)
__device__ __nv_bfloat16 g_Sb [(long)NMAX * KP];      // softmax(S) bf16, padded
__device__ __nv_bfloat16 g_ASb[(long)NMAX * KP];      // A @ S bf16, padded

// ---------------- small utility kernels ------------------------------------
__global__ void k_zero_out(float* out, int total) {
    int i = blockIdx.x * blockDim.x + threadIdx.x;
    if (i < total) out[i] = 0.0f;
}

__global__ void k_cnt_init(int n) {
    int i = blockIdx.x * blockDim.x + threadIdx.x;
    if (i < n) { g_cnt[i] = 0; g_ctmp[i] = 0.0f; }
}

__global__ void k_cnt(const int* __restrict__ row, int e) {
    int i = blockIdx.x * blockDim.x + threadIdx.x;
    if (i < e) atomicAdd(&g_cnt[row[i]], 1);
}

__global__ void k_dinv(int n) {
    int i = blockIdx.x * blockDim.x + threadIdx.x;
    if (i < n) g_dinv[i] = rsqrtf((float)g_cnt[i] + 1.0f);
}

// single-block scan of g_cnt -> g_off (exclusive), g_cur copy, g_off[n]=total
__global__ __launch_bounds__(1024) void k_scan(int n) {
    __shared__ int sm[1024];
    int t = threadIdx.x;
    int chunk = (n + 1023) >> 10;
    int b = t * chunk, eend = min(n, b + chunk);
    int s = 0;
    for (int i = b; i < eend; i++) s += g_cnt[i];
    sm[t] = s;
    __syncthreads();
    for (int off = 1; off < 1024; off <<= 1) {
        int v = (t >= off) ? sm[t - off] : 0;
        __syncthreads();
        sm[t] += v;
        __syncthreads();
    }
    int run = (t > 0) ? sm[t - 1] : 0;
    for (int i = b; i < eend; i++) {
        g_off[i] = run; g_cur[i] = run;
        run += g_cnt[i];
    }
    if (t == 0) g_off[n] = sm[1023];
}

__global__ void k_fill(const int* __restrict__ row, const int* __restrict__ col, int e) {
    int i = blockIdx.x * blockDim.x + threadIdx.x;
    if (i < e) {
        int pos = atomicAdd(&g_cur[row[i]], 1);
        g_eidx[pos] = col[i];
    }
}

// c_tmp[col] += dinv[row]   (bias coefficient c = P @ 1)
__global__ void k_coef(const int* __restrict__ row, const int* __restrict__ col, int e) {
    int i = blockIdx.x * blockDim.x + threadIdx.x;
    if (i < e) atomicAdd(&g_ctmp[col[i]], g_dinv[row[i]]);
}

__global__ void k_cfin(int n) {
    int i = blockIdx.x * blockDim.x + threadIdx.x;
    if (i < n) {
        float dv = g_dinv[i];
        g_c[i] = dv * (dv + g_ctmp[i]);
    }
}

// px = dinv^2 * x (self-loop term); float4 over n*16
__global__ void k_px_self(const float* __restrict__ x, int n) {
    long i = (long)blockIdx.x * blockDim.x + threadIdx.x;
    if (i < (long)n * 16) {
        float dv = g_dinv[i >> 4];
        float w = dv * dv;
        float4 v = __ldg(reinterpret_cast<const float4*>(x) + i);
        reinterpret_cast<float4*>(g_px)[i] =
            make_float4(w * v.x, w * v.y, w * v.z, w * v.w);
    }
}

// px[col] += dinv[row]*dinv[col] * x[row]; 16 lanes per edge (64 floats)
__global__ __launch_bounds__(256) void k_scatter_px(const int* __restrict__ row,
                                                    const int* __restrict__ col,
                                                    const float* __restrict__ x, int e) {
    int t = blockIdx.x * 256 + threadIdx.x;
    int eidx = t >> 4;
    int lane = t & 15;
    if (eidx >= e) return;
    int g = __ldg(&row[eidx]);
    int s = __ldg(&col[eidx]);
    float w = g_dinv[g] * g_dinv[s];
    float4 v = __ldg(reinterpret_cast<const float4*>(x + (long)g * D) + lane);
    float* p = g_px + (long)s * D + lane * 4;
    asm volatile("red.global.add.v4.f32 [%0], {%1,%2,%3,%4};"
                 :: "l"(p), "f"(w * v.x), "f"(w * v.y), "f"(w * v.z), "f"(w * v.w)
                 : "memory");
}

// ---------------- Z = px @ W + c * b^T  (inner dim 64 fixed) ----------------
// MODE 0 -> g_zE (COUT=C), MODE 1 -> g_S (COUT=K)
template <int MODE>
__global__ __launch_bounds__(256) void k_xw(const float* __restrict__ W,
                                            const float* __restrict__ b, int n) {
    constexpr int COUT = (MODE == 0) ? C : K;
    float* out = (MODE == 0) ? g_zE : g_S;

    __shared__ float xs[64][65];
    __shared__ float ws[64][65];

    int n0 = blockIdx.y * 64;
    int c0 = blockIdx.x * 64;
    int tid = threadIdx.x;

    for (int i = tid; i < 64 * 64; i += 256) {
        int r = i >> 6, c = i & 63;
        int nn = n0 + r;
        xs[r][c] = (nn < n) ? g_px[(long)nn * D + c] : 0.0f;
    }
    for (int i = tid; i < 64 * 64; i += 256) {
        int r = i >> 6, c = i & 63;
        int cc = c0 + c;
        ws[r][c] = (cc < COUT) ? W[r * COUT + cc] : 0.0f;
    }
    __syncthreads();

    int tx = tid & 15, ty = tid >> 4;
    float acc[4][4] = {};
#pragma unroll
    for (int k = 0; k < 64; k++) {
        float a[4], bb[4];
#pragma unroll
        for (int i = 0; i < 4; i++) a[i] = xs[ty * 4 + i][k];
#pragma unroll
        for (int j = 0; j < 4; j++) bb[j] = ws[k][tx * 4 + j];
#pragma unroll
        for (int i = 0; i < 4; i++)
#pragma unroll
            for (int j = 0; j < 4; j++) acc[i][j] += a[i] * bb[j];
    }

#pragma unroll
    for (int i = 0; i < 4; i++) {
        int nn = n0 + ty * 4 + i;
        if (nn >= n) continue;
        float cv = g_c[nn];
#pragma unroll
        for (int j = 0; j < 4; j++) {
            int cc = c0 + tx * 4 + j;
            if (cc < COUT) out[(long)nn * COUT + cc] = acc[i][j] + cv * b[cc];
        }
    }
}

// ---------------- row softmax of g_S (K = 500); also writes bf16 copy -------
__global__ __launch_bounds__(256) void k_softmax(int n) {
    int row = blockIdx.x * 8 + (threadIdx.x >> 5);
    int lane = threadIdx.x & 31;
    if (row >= n) return;
    float* p = g_S + (long)row * K;
    __nv_bfloat16* pb = g_Sb + (long)row * KP;

    float vals[16];
    float m = -1e30f;
#pragma unroll
    for (int i = 0; i < 16; i++) {
        int c = lane + i * 32;
        vals[i] = (c < K) ? p[c] : -1e30f;
        m = fmaxf(m, vals[i]);
    }
#pragma unroll
    for (int off = 16; off > 0; off >>= 1)
        m = fmaxf(m, __shfl_xor_sync(0xffffffffu, m, off));

    float sum = 0.0f;
#pragma unroll
    for (int i = 0; i < 16; i++) {
        int c = lane + i * 32;
        vals[i] = (c < K) ? expf(vals[i] - m) : 0.0f;
        sum += vals[i];
    }
#pragma unroll
    for (int off = 16; off > 0; off >>= 1)
        sum += __shfl_xor_sync(0xffffffffu, sum, off);

    float inv = 1.0f / sum;
#pragma unroll
    for (int i = 0; i < 16; i++) {
        int c = lane + i * 32;
        float v = vals[i] * inv;
        if (c < K) p[c] = v;
        pb[c] = __float2bfloat16((c < K) ? v : 0.0f);  // c <= 511 always
    }
}

// ---------------- AS[i] = sum_{e in out(i)} Sb[col_e]  (bf16 out) -----------
__global__ __launch_bounds__(128) void k_AS_gather(int n) {
    int node = blockIdx.x;
    if (node >= n) return;
    int beg = g_off[node], end = g_off[node + 1];
    int c = threadIdx.x;          // handles cols 4c..4c+3
    float a0 = 0.f, a1 = 0.f, a2 = 0.f, a3 = 0.f;
    const uint2* base = reinterpret_cast<const uint2*>(g_Sb);
    for (int e = beg; e < end; e++) {
        int src = __ldg(&g_eidx[e]);
        uint2 v = __ldg(&base[(long)src * (KP / 4) + c]);
        __nv_bfloat162 p0 = *reinterpret_cast<__nv_bfloat162*>(&v.x);
        __nv_bfloat162 p1 = *reinterpret_cast<__nv_bfloat162*>(&v.y);
        float2 f0 = __bfloat1622float2(p0);
        float2 f1 = __bfloat1622float2(p1);
        a0 += f0.x; a1 += f0.y; a2 += f1.x; a3 += f1.y;
    }
    __nv_bfloat162 r0 = __floats2bfloat162_rn(a0, a1);
    __nv_bfloat162 r1 = __floats2bfloat162_rn(a2, a3);
    uint2 o;
    o.x = *reinterpret_cast<uint32_t*>(&r0);
    o.y = *reinterpret_cast<uint32_t*>(&r1);
    reinterpret_cast<uint2*>(g_ASb)[(long)node * (KP / 4) + c] = o;
}

// ---------------- next_X = S^T @ zE  (f32x2 packed, split-K) ----------------
__global__ __launch_bounds__(256) void k_stm0(float* __restrict__ out, int n,
                                              int nPerSplit) {
    constexpr int BN = 64, TN = 4, BM = 128, BK = 32;
    __shared__ float Ss[BK][BM];
    __shared__ float Ms[BK][BN];

    const int m0 = blockIdx.y * BM;
    const int n0 = 0;
    const int nStart = blockIdx.z * nPerSplit;
    const int nEnd = min(n, nStart + nPerSplit);
    const int tid = threadIdx.x;
    const int txm = tid & 15;
    const int tyn = tid >> 4;

    unsigned long long acc[2][2][TN];
#pragma unroll
    for (int a = 0; a < 2; a++)
#pragma unroll
        for (int p = 0; p < 2; p++)
#pragma unroll
            for (int j = 0; j < TN; j++) acc[a][p][j] = 0ull;

    uint32_t sS = (uint32_t)__cvta_generic_to_shared((void*)&Ss[0][0]);

    for (int nb = nStart; nb < nEnd; nb += BK) {
        for (int i = tid; i < BK * (BM / 4); i += 256) {
            int r = i >> 5;
            int c4 = i & 31;
            int kk = nb + r;
            int mf4 = (m0 >> 2) + c4;
            float4 v = make_float4(0.f, 0.f, 0.f, 0.f);
            if (kk < nEnd && mf4 < (K >> 2))
                v = *reinterpret_cast<const float4*>(g_S + (long)kk * K + (mf4 << 2));
            *reinterpret_cast<float4*>(&Ss[r][c4 << 2]) = v;
        }
        for (int i = tid; i < BK * (BN / 4); i += 256) {
            int r = i / (BN / 4);
            int c4 = i % (BN / 4);
            int kk = nb + r;
            float4 v = make_float4(0.f, 0.f, 0.f, 0.f);
            if (kk < nEnd)
                v = *reinterpret_cast<const float4*>(g_zE + (long)kk * C + (c4 << 2));
            *reinterpret_cast<float4*>(&Ms[r][c4 << 2]) = v;
        }
        __syncthreads();

#pragma unroll 8
        for (int kk = 0; kk < BK; kk++) {
            unsigned long long a2[2][2];
#pragma unroll
            for (int ch = 0; ch < 2; ch++)
#pragma unroll
                for (int p = 0; p < 2; p++) {
                    uint32_t addr = sS + ((kk * BM + ch * 64 + txm * 4 + p * 2) << 2);
                    asm volatile("ld.shared.b64 %0, [%1];" : "=l"(a2[ch][p]) : "r"(addr));
                }
            float bv[TN];
            float4 b4 = *reinterpret_cast<const float4*>(&Ms[kk][tyn * TN]);
            bv[0] = b4.x; bv[1] = b4.y; bv[2] = b4.z; bv[3] = b4.w;
#pragma unroll
            for (int j = 0; j < TN; j++) {
                unsigned long long bb;
                asm("mov.b64 %0, {%1, %2};" : "=l"(bb) : "f"(bv[j]), "f"(bv[j]));
#pragma unroll
                for (int ch = 0; ch < 2; ch++)
#pragma unroll
                    for (int p = 0; p < 2; p++)
                        asm("fma.rn.f32x2 %0, %1, %2, %0;"
                            : "+l"(acc[ch][p][j]) : "l"(a2[ch][p]), "l"(bb));
            }
        }
        __syncthreads();
    }

#pragma unroll
    for (int ch = 0; ch < 2; ch++)
#pragma unroll
        for (int p = 0; p < 2; p++)
#pragma unroll
            for (int j = 0; j < TN; j++) {
                float lo, hi;
                asm("mov.b64 {%0, %1}, %2;" : "=f"(lo), "=f"(hi) : "l"(acc[ch][p][j]));
                int m = m0 + ch * 64 + txm * 4 + p * 2;
                int nn = n0 + tyn * TN + j;
                if (m < K)     atomicAdd(&out[(long)m * C + nn], lo);
                if (m + 1 < K) atomicAdd(&out[(long)(m + 1) * C + nn], hi);
            }
}

// ---------------- next_A = S^T @ AS  (bf16 mma.sync, split-K) ---------------
// D[m,n] = sum_k Sb[k][m] * ASb[k][n]; tiles staged as [k][m]/[k][n] (bf16),
// fragments via ldmatrix.x4.trans. BM=BN=128, BK=32, 8 warps (2m x 4n).
__global__ __launch_bounds__(256) void k_stm1(float* __restrict__ out, int n,
                                              int nPerSplit) {
    constexpr int PAD = 136;  // 272B row stride -> conflict-free ldmatrix
    __shared__ __align__(16) __nv_bfloat16 As[32][PAD];
    __shared__ __align__(16) __nv_bfloat16 Bs[32][PAD];

    const int m0 = blockIdx.y * 128;
    const int n0 = blockIdx.x * 128;
    const int nStart = blockIdx.z * nPerSplit;
    const int nEnd = min(n, nStart + nPerSplit);
    const int tid = threadIdx.x;
    const int wid = tid >> 5, lane = tid & 31;
    const int wm = wid & 1, wn = wid >> 1;

    float acc[4][4][4] = {};

    uint32_t sA = (uint32_t)__cvta_generic_to_shared((void*)&As[0][0]);
    uint32_t sB = (uint32_t)__cvta_generic_to_shared((void*)&Bs[0][0]);

    for (int k0 = nStart; k0 < nEnd; k0 += 32) {
        // stage As[r][0..127] = Sb[k0+r][m0..m0+127], Bs from ASb
#pragma unroll
        for (int i = tid; i < 32 * 16; i += 256) {
            int r = i >> 4, q = i & 15;
            int kk = k0 + r;
            uint4 v = make_uint4(0, 0, 0, 0);
            if (kk < nEnd)
                v = *reinterpret_cast<const uint4*>(g_Sb + (long)kk * KP + m0 + q * 8);
            *reinterpret_cast<uint4*>(&As[r][q * 8]) = v;
        }
#pragma unroll
        for (int i = tid; i < 32 * 16; i += 256) {
            int r = i >> 4, q = i & 15;
            int kk = k0 + r;
            uint4 v = make_uint4(0, 0, 0, 0);
            if (kk < nEnd)
                v = *reinterpret_cast<const uint4*>(g_ASb + (long)kk * KP + n0 + q * 8);
            *reinterpret_cast<uint4*>(&Bs[r][q * 8]) = v;
        }
        __syncthreads();

#pragma unroll
        for (int s = 0; s < 2; s++) {
            // A fragments: 4 m16 tiles
            uint32_t af[4][4];
            int ra = s * 16 + (lane & 7) + ((lane >> 4) << 3);
            int ca = wm * 64 + (((lane >> 3) & 1) << 3);
#pragma unroll
            for (int t = 0; t < 4; t++) {
                uint32_t addr = sA + (uint32_t)(ra * PAD + ca + t * 16) * 2;
                asm volatile("ldmatrix.sync.aligned.m8n8.x4.trans.shared.b16 "
                             "{%0,%1,%2,%3}, [%4];"
                             : "=r"(af[t][0]), "=r"(af[t][1]), "=r"(af[t][2]), "=r"(af[t][3])
                             : "r"(addr));
            }
            // B fragments: 2 groups of n16 (4 n8 tiles)
            uint32_t bf[2][4];
            int rb = s * 16 + (lane & 7) + (((lane >> 3) & 1) << 3);
            int cb = wn * 32 + ((lane >> 4) << 3);
#pragma unroll
            for (int g = 0; g < 2; g++) {
                uint32_t addr = sB + (uint32_t)(rb * PAD + cb + g * 16) * 2;
                asm volatile("ldmatrix.sync.aligned.m8n8.x4.trans.shared.b16 "
                             "{%0,%1,%2,%3}, [%4];"
                             : "=r"(bf[g][0]), "=r"(bf[g][1]), "=r"(bf[g][2]), "=r"(bf[g][3])
                             : "r"(addr));
            }
#pragma unroll
            for (int t = 0; t < 4; t++)
#pragma unroll
                for (int j = 0; j < 4; j++) {
                    uint32_t b0 = bf[j >> 1][(j & 1) * 2];
                    uint32_t b1 = bf[j >> 1][(j & 1) * 2 + 1];
                    asm volatile(
                        "mma.sync.aligned.m16n8k16.row.col.f32.bf16.bf16.f32 "
                        "{%0,%1,%2,%3}, {%4,%5,%6,%7}, {%8,%9}, {%0,%1,%2,%3};"
                        : "+f"(acc[t][j][0]), "+f"(acc[t][j][1]),
                          "+f"(acc[t][j][2]), "+f"(acc[t][j][3])
                        : "r"(af[t][0]), "r"(af[t][1]), "r"(af[t][2]), "r"(af[t][3]),
                          "r"(b0), "r"(b1));
                }
        }
        __syncthreads();
    }

    // epilogue: atomic accumulate into out[K x K] (guard padding)
#pragma unroll
    for (int t = 0; t < 4; t++) {
        int mA = m0 + wm * 64 + t * 16 + (lane >> 2);
#pragma unroll
        for (int j = 0; j < 4; j++) {
            int nn = n0 + wn * 32 + j * 8 + (lane & 3) * 2;
            if (nn < K) {
                if (mA < K)     atomicAdd(&out[(long)mA * K + nn], acc[t][j][0]);
                if (mA + 8 < K) atomicAdd(&out[(long)(mA + 8) * K + nn], acc[t][j][2]);
            }
            if (nn + 1 < K) {
                if (mA < K)     atomicAdd(&out[(long)mA * K + nn + 1], acc[t][j][1]);
                if (mA + 8 < K) atomicAdd(&out[(long)(mA + 8) * K + nn + 1], acc[t][j][3]);
            }
        }
    }
}

// ---------------- launch -----------------------------------------------------
extern "C" void kernel_launch(void* const* d_in, const int* in_sizes, int n_in,
                              void* d_out, int out_size) {
    const float* x  = (const float*)d_in[0];
    const int*   ei = (const int*)d_in[1];
    const float* We = (const float*)d_in[2];
    const float* be = (const float*)d_in[3];
    const float* Wa = (const float*)d_in[4];
    const float* ba = (const float*)d_in[5];
    float* out = (float*)d_out;

    int n = in_sizes[0] / D;
    int e = in_sizes[1] / 2;
    const int* row = ei;       // source j
    const int* col = ei + e;   // target i

    // zero output (poisoned by harness)
    k_zero_out<<<(out_size + 511) / 512, 512>>>(out, out_size);

    // degree counts (int), dinv, CSR over row
    k_cnt_init<<<(n + 255) / 256, 256>>>(n);
    k_cnt<<<(e + 255) / 256, 256>>>(row, e);
    k_dinv<<<(n + 255) / 256, 256>>>(n);
    k_scan<<<1, 1024>>>(n);
    k_fill<<<(e + 255) / 256, 256>>>(row, col, e);

    // px = P @ x
    k_px_self<<<(n * 16 + 255) / 256, 256>>>(x, n);
    k_scatter_px<<<(e * 16 + 255) / 256, 256>>>(row, col, x, e);

    // c = P @ 1
    k_coef<<<(e + 255) / 256, 256>>>(row, col, e);
    k_cfin<<<(n + 255) / 256, 256>>>(n);

    // Z_assign = px@Wa + c ba^T ; Z_embed = px@We + c be^T
    {
        dim3 gA((K + 63) / 64, (n + 63) / 64);
        k_xw<1><<<gA, 256>>>(Wa, ba, n);
        dim3 gE((C + 63) / 64, (n + 63) / 64);
        k_xw<0><<<gE, 256>>>(We, be, n);
    }

    // S = softmax rowwise (f32 + bf16 copies)
    k_softmax<<<(n + 7) / 8, 256>>>(n);

    // AS = A @ S via CSR gather (bf16)
    k_AS_gather<<<n, 128>>>(n);

    // next_X = S^T @ zE  [K, C]  (f32x2)
    {
        int splits = 72;
        int nPer = (n + splits - 1) / splits;
        dim3 g(1, 4, splits);
        k_stm0<<<g, 256>>>(out, n, nPer);
    }
    // next_A = S^T @ AS  [K, K]  (bf16 mma)
    {
        int splits = 20;
        int nPer = (n + splits - 1) / splits;
        dim3 g(4, 4, splits);
        k_stm1<<<g, 256>>>(out + K * C, n, nPer);
    }
}